// round 1
// baseline (speedup 1.0000x reference)
#include <cuda_runtime.h>
#include <math.h>

#define B 2
#define S 2048
#define D 1024
#define H 16
#define DK 64
#define NTOK (B * S)

// Scratch (allocation-free rule: __device__ globals)
__device__ float g_Q[(size_t)NTOK * D];
__device__ float g_K[(size_t)NTOK * D];
__device__ float g_V[(size_t)NTOK * D];
__device__ float g_X[(size_t)NTOK * D];

// ---------------------------------------------------------------------------
// SGEMM: C[M x N] = A[M x K] * W[K x N], row-major. M=4096, N=K=1024.
// 128x128 block tile, BK=8, 256 threads, 8x8 per-thread microtile.
// ---------------------------------------------------------------------------
__global__ void __launch_bounds__(256) sgemm_kernel(
    const float* __restrict__ A, const float* __restrict__ W,
    float* __restrict__ C) {
    __shared__ float As[8][132];  // transposed: As[k][row]
    __shared__ float Bs[8][132];  // natural:    Bs[k][col]

    const int tid = threadIdx.x;
    const int tx = tid & 15;       // 0..15 -> col groups
    const int ty = tid >> 4;       // 0..15 -> row groups
    const int rowBlock = blockIdx.y * 128;
    const int colBlock = blockIdx.x * 128;

    const int arow = tid >> 1;         // 0..127
    const int acol = (tid & 1) * 4;    // 0 or 4
    const int brow = tid >> 5;         // 0..7
    const int bcol = (tid & 31) * 4;   // 0..124

    const float* Aptr = A + (size_t)(rowBlock + arow) * D + acol;
    const float* Bptr = W + (size_t)brow * D + colBlock + bcol;

    float acc[8][8];
#pragma unroll
    for (int i = 0; i < 8; i++)
#pragma unroll
        for (int j = 0; j < 8; j++) acc[i][j] = 0.0f;

    for (int k0 = 0; k0 < D; k0 += 8) {
        float4 a4 = *(const float4*)(Aptr + k0);
        float4 b4 = *(const float4*)(Bptr + (size_t)k0 * D);
        As[acol + 0][arow] = a4.x;
        As[acol + 1][arow] = a4.y;
        As[acol + 2][arow] = a4.z;
        As[acol + 3][arow] = a4.w;
        *(float4*)&Bs[brow][bcol] = b4;
        __syncthreads();

#pragma unroll
        for (int kk = 0; kk < 8; kk++) {
            float a[8], b[8];
            *(float4*)(a)     = *(const float4*)&As[kk][ty * 4];
            *(float4*)(a + 4) = *(const float4*)&As[kk][64 + ty * 4];
            *(float4*)(b)     = *(const float4*)&Bs[kk][tx * 4];
            *(float4*)(b + 4) = *(const float4*)&Bs[kk][64 + tx * 4];
#pragma unroll
            for (int i = 0; i < 8; i++)
#pragma unroll
                for (int j = 0; j < 8; j++) acc[i][j] += a[i] * b[j];
        }
        __syncthreads();
    }

#pragma unroll
    for (int i = 0; i < 8; i++) {
        int r = rowBlock + ((i < 4) ? (ty * 4 + i) : (64 + ty * 4 + i - 4));
        float4 v0 = make_float4(acc[i][0], acc[i][1], acc[i][2], acc[i][3]);
        float4 v1 = make_float4(acc[i][4], acc[i][5], acc[i][6], acc[i][7]);
        *(float4*)&C[(size_t)r * D + colBlock + tx * 4] = v0;
        *(float4*)&C[(size_t)r * D + colBlock + 64 + tx * 4] = v1;
    }
}

// ---------------------------------------------------------------------------
// Flash attention (fp32, online softmax). One CTA per (b, h, 64-row q tile).
// 256 threads as 16x16 grid; each thread owns a 4(q) x 4 microtile.
// ---------------------------------------------------------------------------
#define SMP 68  // padded row stride (floats); multiple of 4 for float4 access
#define ATTN_SMEM (4 * 64 * SMP * sizeof(float))

__global__ void __launch_bounds__(256) attn_kernel(const int* __restrict__ mask) {
    extern __shared__ float sm[];
    float* Qs = sm;                 // transposed: Qs[k*SMP + qrow]
    float* Ks = Qs + 64 * SMP;      // transposed: Ks[k*SMP + kcol]
    float* Vs = Ks + 64 * SMP;      // natural:    Vs[krow*SMP + d]
    float* Ps = Vs + 64 * SMP;      // transposed: Ps[kcol*SMP + qrow]

    const int tid = threadIdx.x;
    const int tx = tid & 15;
    const int ty = tid >> 4;
    const int q0 = blockIdx.x * 64;
    const int h = blockIdx.y;
    const int b = blockIdx.z;

    const float* Qg = g_Q + ((size_t)(b * S) + q0) * D + h * DK;
    const float* Kg = g_K + (size_t)(b * S) * D + h * DK;
    const float* Vg = g_V + (size_t)(b * S) * D + h * DK;
    const int* Mg = mask + (size_t)b * S * S;

    // Load Q tile (64x64), store k-transposed
#pragma unroll
    for (int it = 0; it < 4; it++) {
        int idx = it * 1024 + tid * 4;
        int r = idx >> 6, c = idx & 63;
        float4 qv = *(const float4*)(Qg + (size_t)r * D + c);
        Qs[(c + 0) * SMP + r] = qv.x;
        Qs[(c + 1) * SMP + r] = qv.y;
        Qs[(c + 2) * SMP + r] = qv.z;
        Qs[(c + 3) * SMP + r] = qv.w;
    }

    float m_i[4], l_i[4], o[4][4];
#pragma unroll
    for (int i = 0; i < 4; i++) {
        m_i[i] = -3.0e38f;
        l_i[i] = 0.0f;
#pragma unroll
        for (int j = 0; j < 4; j++) o[i][j] = 0.0f;
    }

    for (int kt = 0; kt < 32; kt++) {
        const int k0 = kt * 64;
        __syncthreads();  // prior PV done; also orders Q-tile stores (kt=0)

        // Load K (transposed) and V (natural) tiles
#pragma unroll
        for (int it = 0; it < 4; it++) {
            int idx = it * 1024 + tid * 4;
            int r = idx >> 6, c = idx & 63;
            float4 kv = *(const float4*)(Kg + (size_t)(k0 + r) * D + c);
            Ks[(c + 0) * SMP + r] = kv.x;
            Ks[(c + 1) * SMP + r] = kv.y;
            Ks[(c + 2) * SMP + r] = kv.z;
            Ks[(c + 3) * SMP + r] = kv.w;
            float4 vv = *(const float4*)(Vg + (size_t)(k0 + r) * D + c);
            *(float4*)(Vs + r * SMP + c) = vv;
        }
        __syncthreads();

        // S = Q K^T
        float s[4][4];
#pragma unroll
        for (int i = 0; i < 4; i++)
#pragma unroll
            for (int j = 0; j < 4; j++) s[i][j] = 0.0f;

#pragma unroll 16
        for (int kk = 0; kk < 64; kk++) {
            float4 aa = *(const float4*)(Qs + kk * SMP + ty * 4);
            float4 bb = *(const float4*)(Ks + kk * SMP + tx * 4);
            float a[4] = {aa.x, aa.y, aa.z, aa.w};
            float bv[4] = {bb.x, bb.y, bb.z, bb.w};
#pragma unroll
            for (int i = 0; i < 4; i++)
#pragma unroll
                for (int j = 0; j < 4; j++) s[i][j] += a[i] * bv[j];
        }

        // scale + mask
#pragma unroll
        for (int i = 0; i < 4; i++) {
            int4 mm = *(const int4*)(Mg + (size_t)(q0 + ty * 4 + i) * S + k0 + tx * 4);
            s[i][0] = (mm.x != 0) ? s[i][0] * 0.125f : -1.0e9f;
            s[i][1] = (mm.y != 0) ? s[i][1] * 0.125f : -1.0e9f;
            s[i][2] = (mm.z != 0) ? s[i][2] * 0.125f : -1.0e9f;
            s[i][3] = (mm.w != 0) ? s[i][3] * 0.125f : -1.0e9f;
        }

        // online softmax (rows split across 16 tx lanes within half-warp)
#pragma unroll
        for (int i = 0; i < 4; i++) {
            float tm = fmaxf(fmaxf(s[i][0], s[i][1]), fmaxf(s[i][2], s[i][3]));
#pragma unroll
            for (int off = 1; off < 16; off <<= 1)
                tm = fmaxf(tm, __shfl_xor_sync(0xffffffffu, tm, off));
            float mnew = fmaxf(m_i[i], tm);
            float corr = __expf(m_i[i] - mnew);
            m_i[i] = mnew;
            float rs = 0.0f;
#pragma unroll
            for (int j = 0; j < 4; j++) {
                s[i][j] = __expf(s[i][j] - mnew);
                rs += s[i][j];
            }
#pragma unroll
            for (int off = 1; off < 16; off <<= 1)
                rs += __shfl_xor_sync(0xffffffffu, rs, off);
            l_i[i] = l_i[i] * corr + rs;
#pragma unroll
            for (int j = 0; j < 4; j++) o[i][j] *= corr;
        }

        // store P transposed: Ps[kcol * SMP + qrow]
#pragma unroll
        for (int j = 0; j < 4; j++) {
            float4 pv = make_float4(s[0][j], s[1][j], s[2][j], s[3][j]);
            *(float4*)(Ps + (tx * 4 + j) * SMP + ty * 4) = pv;
        }
        __syncthreads();

        // O += P V
#pragma unroll 16
        for (int cc = 0; cc < 64; cc++) {
            float4 aa = *(const float4*)(Ps + cc * SMP + ty * 4);
            float4 bb = *(const float4*)(Vs + cc * SMP + tx * 4);
            float a[4] = {aa.x, aa.y, aa.z, aa.w};
            float bv[4] = {bb.x, bb.y, bb.z, bb.w};
#pragma unroll
            for (int i = 0; i < 4; i++)
#pragma unroll
                for (int j = 0; j < 4; j++) o[i][j] += a[i] * bv[j];
        }
    }

    // epilogue: normalize, write to concat-head layout X[b, s, h*DK + d]
    float* Xg = g_X + ((size_t)(b * S) + q0) * D + h * DK;
#pragma unroll
    for (int i = 0; i < 4; i++) {
        float inv = 1.0f / l_i[i];
        float4 ov = make_float4(o[i][0] * inv, o[i][1] * inv, o[i][2] * inv,
                                o[i][3] * inv);
        *(float4*)(Xg + (size_t)(ty * 4 + i) * D + tx * 4) = ov;
    }
}

// ---------------------------------------------------------------------------
extern "C" void kernel_launch(void* const* d_in, const int* in_sizes, int n_in,
                              void* d_out, int out_size) {
    const float* q = (const float*)d_in[0];
    const float* k = (const float*)d_in[1];
    const float* v = (const float*)d_in[2];
    const int* mask = (const int*)d_in[3];
    const float* Wq = (const float*)d_in[4];
    const float* Wk = (const float*)d_in[5];
    const float* Wv = (const float*)d_in[6];
    const float* Wo = (const float*)d_in[7];
    float* out = (float*)d_out;

    float *Q, *K, *V, *X;
    cudaGetSymbolAddress((void**)&Q, g_Q);
    cudaGetSymbolAddress((void**)&K, g_K);
    cudaGetSymbolAddress((void**)&V, g_V);
    cudaGetSymbolAddress((void**)&X, g_X);

    dim3 gemmGrid(D / 128, NTOK / 128);  // (8, 32)
    sgemm_kernel<<<gemmGrid, 256>>>(q, Wq, Q);
    sgemm_kernel<<<gemmGrid, 256>>>(k, Wk, K);
    sgemm_kernel<<<gemmGrid, 256>>>(v, Wv, V);

    cudaFuncSetAttribute(attn_kernel, cudaFuncAttributeMaxDynamicSharedMemorySize,
                         (int)ATTN_SMEM);
    attn_kernel<<<dim3(S / 64, H, B), 256, ATTN_SMEM>>>(mask);

    sgemm_kernel<<<gemmGrid, 256>>>(X, Wo, out);
}

// round 3
// speedup vs baseline: 1.3892x; 1.3892x over previous
#include <cuda_runtime.h>
#include <cuda_bf16.h>
#include <stdint.h>
#include <math.h>

#define B 2
#define S 2048
#define D 1024
#define H 16
#define DK 64
#define NTOK (B * S)

// Scratch (allocation-free rule: __device__ globals)
__device__ float g_Q[(size_t)NTOK * D];
__device__ float g_K[(size_t)NTOK * D];
__device__ float g_V[(size_t)NTOK * D];
__device__ float g_X[(size_t)NTOK * D];
__device__ __nv_bfloat16 g_Ah[(size_t)NTOK * D];
__device__ __nv_bfloat16 g_Al[(size_t)NTOK * D];
__device__ __nv_bfloat16 g_Bh[(size_t)D * D];
__device__ __nv_bfloat16 g_Bl[(size_t)D * D];

// ---------------------------------------------------------------------------
// helpers (plain sm_80-level PTX only: ldmatrix / mma.sync / cp.async)
// ---------------------------------------------------------------------------
__device__ __forceinline__ uint32_t smem_u32(const void* p) {
    uint32_t a;
    asm("{ .reg .u64 t; cvta.to.shared.u64 t, %1; cvt.u32.u64 %0, t; }"
        : "=r"(a) : "l"(p));
    return a;
}

#define LDX4(r, addr)                                                          \
    asm volatile(                                                              \
        "ldmatrix.sync.aligned.m8n8.x4.shared.b16 {%0,%1,%2,%3}, [%4];"        \
        : "=r"((r)[0]), "=r"((r)[1]), "=r"((r)[2]), "=r"((r)[3])               \
        : "r"(addr))

#define MMA16816(d, a, b)                                                      \
    asm volatile(                                                              \
        "mma.sync.aligned.m16n8k16.row.col.f32.bf16.bf16.f32 "                 \
        "{%0,%1,%2,%3},{%4,%5,%6,%7},{%8,%9},{%0,%1,%2,%3};"                   \
        : "+f"((d)[0]), "+f"((d)[1]), "+f"((d)[2]), "+f"((d)[3])               \
        : "r"((a)[0]), "r"((a)[1]), "r"((a)[2]), "r"((a)[3]),                  \
          "r"((b)[0]), "r"((b)[1]))

#define CP_ASYNC16(dst, src)                                                   \
    asm volatile("cp.async.cg.shared.global [%0], [%1], 16;" ::"r"(dst),       \
                 "l"(src))
#define CP_COMMIT() asm volatile("cp.async.commit_group;" ::: "memory")
#define CP_WAIT_ALL() asm volatile("cp.async.wait_group 0;" ::: "memory")

// ---------------------------------------------------------------------------
// Split kernels: fp32 -> bf16 hi + bf16 lo (residual)
// ---------------------------------------------------------------------------
__global__ void __launch_bounds__(256) split_a_kernel(
    const float* __restrict__ A, __nv_bfloat16* __restrict__ Ah,
    __nv_bfloat16* __restrict__ Al) {
    int i = blockIdx.x * 256 + threadIdx.x;
    float x = A[i];
    __nv_bfloat16 h = __float2bfloat16(x);
    Ah[i] = h;
    Al[i] = __float2bfloat16(x - __bfloat162float(h));
}

// W [K,N] row-major -> Wt [N,K] row-major, split into hi/lo bf16
__global__ void __launch_bounds__(256) split_wt_kernel(
    const float* __restrict__ W, __nv_bfloat16* __restrict__ Bh,
    __nv_bfloat16* __restrict__ Bl) {
    __shared__ float t[32][33];
    const int n0 = blockIdx.x * 32, k0 = blockIdx.y * 32;
    const int tx = threadIdx.x, ty = threadIdx.y;  // 32 x 8
#pragma unroll
    for (int r = ty; r < 32; r += 8)
        t[r][tx] = W[(size_t)(k0 + r) * D + n0 + tx];
    __syncthreads();
#pragma unroll
    for (int r = ty; r < 32; r += 8) {
        float x = t[tx][r];  // = W[k0+tx][n0+r]
        __nv_bfloat16 h = __float2bfloat16(x);
        size_t o = (size_t)(n0 + r) * D + k0 + tx;
        Bh[o] = h;
        Bl[o] = __float2bfloat16(x - __bfloat162float(h));
    }
}

// ---------------------------------------------------------------------------
// mma.sync GEMM: C[M x N] = (Ah+Al)[M x K] * (Bh+Bl)^T (B stored [N,K]).
// CTA 128x128, BK=64, 8 warps (2m x 4n), warp tile 64x32.
// SMEM: per stage 4 tiles (AH, AL, BH, BL) of 128 rows x 128B, SW128 swizzle.
// ---------------------------------------------------------------------------
#define TILE_BYTES 16384
#define STAGE_BYTES 65536
#define GEMM_SMEM (2 * STAGE_BYTES)

__global__ void __launch_bounds__(256, 1) gemm_mma_kernel(
    const __nv_bfloat16* __restrict__ Ah, const __nv_bfloat16* __restrict__ Al,
    const __nv_bfloat16* __restrict__ Bh, const __nv_bfloat16* __restrict__ Bl,
    float* __restrict__ C) {
    extern __shared__ char sm[];
    const uint32_t sb = smem_u32(sm);
    const int tid = threadIdx.x;
    const int lid = tid & 31;
    const int wid = tid >> 5;
    const int wm = wid & 1;      // 0..1
    const int wn = wid >> 1;     // 0..3
    const int rowB = blockIdx.y * 128;
    const int colB = blockIdx.x * 128;

    float d[4][4][4];
#pragma unroll
    for (int mi = 0; mi < 4; mi++)
#pragma unroll
        for (int nj = 0; nj < 4; nj++)
#pragma unroll
            for (int e = 0; e < 4; e++) d[mi][nj][e] = 0.0f;

    auto load_stage = [&](int stg, int kt) {
        const uint32_t base = sb + stg * STAGE_BYTES;
#pragma unroll
        for (int i = 0; i < 16; i++) {
            const int idx = tid + i * 256;
            const int tile = idx >> 10;          // 0:AH 1:AL 2:BH 3:BL
            const int r = (idx >> 3) & 127;
            const int c = idx & 7;
            const __nv_bfloat16* g;
            if (tile == 0)      g = Ah + (size_t)(rowB + r) * D;
            else if (tile == 1) g = Al + (size_t)(rowB + r) * D;
            else if (tile == 2) g = Bh + (size_t)(colB + r) * D;
            else                g = Bl + (size_t)(colB + r) * D;
            g += kt * 64 + c * 8;
            const uint32_t dst =
                base + tile * TILE_BYTES + r * 128 + ((c ^ (r & 7)) << 4);
            CP_ASYNC16(dst, g);
        }
        CP_COMMIT();
    };

    load_stage(0, 0);

    for (int kt = 0; kt < 16; kt++) {
        const int cur = kt & 1;
        CP_WAIT_ALL();
        __syncthreads();
        if (kt + 1 < 16) load_stage(cur ^ 1, kt + 1);

        const uint32_t sA = sb + cur * STAGE_BYTES;               // AH
        const uint32_t sB = sA + 2 * TILE_BYTES;                  // BH

#pragma unroll
        for (int kk = 0; kk < 4; kk++) {
            uint32_t ah[4][4], al[4][4], bh[4][2], bl[4][2];
#pragma unroll
            for (int mi = 0; mi < 4; mi++) {
                const int row = wm * 64 + mi * 16 + (lid & 15);
                const int c = kk * 2 + (lid >> 4);
                const uint32_t off = row * 128 + ((c ^ (row & 7)) << 4);
                LDX4(ah[mi], sA + off);
                LDX4(al[mi], sA + TILE_BYTES + off);
            }
#pragma unroll
            for (int jj = 0; jj < 2; jj++) {
                const int m = lid >> 3;
                const int n = wn * 32 + jj * 16 + ((m >> 1) << 3) + (lid & 7);
                const int c = kk * 2 + (m & 1);
                const uint32_t off = n * 128 + ((c ^ (n & 7)) << 4);
                uint32_t t[4];
                LDX4(t, sB + off);
                bh[jj * 2][0] = t[0];
                bh[jj * 2][1] = t[1];
                bh[jj * 2 + 1][0] = t[2];
                bh[jj * 2 + 1][1] = t[3];
                LDX4(t, sB + TILE_BYTES + off);
                bl[jj * 2][0] = t[0];
                bl[jj * 2][1] = t[1];
                bl[jj * 2 + 1][0] = t[2];
                bl[jj * 2 + 1][1] = t[3];
            }
#pragma unroll
            for (int mi = 0; mi < 4; mi++)
#pragma unroll
                for (int nj = 0; nj < 4; nj++) {
                    MMA16816(d[mi][nj], ah[mi], bh[nj]);
                    MMA16816(d[mi][nj], ah[mi], bl[nj]);
                    MMA16816(d[mi][nj], al[mi], bh[nj]);
                }
        }
    }

    // epilogue: write fp32 C
#pragma unroll
    for (int mi = 0; mi < 4; mi++) {
        const int r0 = rowB + wm * 64 + mi * 16 + (lid >> 2);
#pragma unroll
        for (int nj = 0; nj < 4; nj++) {
            const int col = colB + wn * 32 + nj * 8 + (lid & 3) * 2;
            *(float2*)(C + (size_t)r0 * D + col) =
                make_float2(d[mi][nj][0], d[mi][nj][1]);
            *(float2*)(C + (size_t)(r0 + 8) * D + col) =
                make_float2(d[mi][nj][2], d[mi][nj][3]);
        }
    }
}

// ---------------------------------------------------------------------------
// Flash attention (fp32, online softmax) — unchanged.
// ---------------------------------------------------------------------------
#define SMP 68
#define ATTN_SMEM (4 * 64 * SMP * sizeof(float))

__global__ void __launch_bounds__(256) attn_kernel(const int* __restrict__ mask) {
    extern __shared__ float smf[];
    float* Qs = smf;
    float* Ks = Qs + 64 * SMP;
    float* Vs = Ks + 64 * SMP;
    float* Ps = Vs + 64 * SMP;

    const int tid = threadIdx.x;
    const int tx = tid & 15;
    const int ty = tid >> 4;
    const int q0 = blockIdx.x * 64;
    const int h = blockIdx.y;
    const int b = blockIdx.z;

    const float* Qg = g_Q + ((size_t)(b * S) + q0) * D + h * DK;
    const float* Kg = g_K + (size_t)(b * S) * D + h * DK;
    const float* Vg = g_V + (size_t)(b * S) * D + h * DK;
    const int* Mg = mask + (size_t)b * S * S;

#pragma unroll
    for (int it = 0; it < 4; it++) {
        int idx = it * 1024 + tid * 4;
        int r = idx >> 6, c = idx & 63;
        float4 qv = *(const float4*)(Qg + (size_t)r * D + c);
        Qs[(c + 0) * SMP + r] = qv.x;
        Qs[(c + 1) * SMP + r] = qv.y;
        Qs[(c + 2) * SMP + r] = qv.z;
        Qs[(c + 3) * SMP + r] = qv.w;
    }

    float m_i[4], l_i[4], o[4][4];
#pragma unroll
    for (int i = 0; i < 4; i++) {
        m_i[i] = -3.0e38f;
        l_i[i] = 0.0f;
#pragma unroll
        for (int j = 0; j < 4; j++) o[i][j] = 0.0f;
    }

    for (int kt = 0; kt < 32; kt++) {
        const int k0 = kt * 64;
        __syncthreads();

#pragma unroll
        for (int it = 0; it < 4; it++) {
            int idx = it * 1024 + tid * 4;
            int r = idx >> 6, c = idx & 63;
            float4 kv = *(const float4*)(Kg + (size_t)(k0 + r) * D + c);
            Ks[(c + 0) * SMP + r] = kv.x;
            Ks[(c + 1) * SMP + r] = kv.y;
            Ks[(c + 2) * SMP + r] = kv.z;
            Ks[(c + 3) * SMP + r] = kv.w;
            float4 vv = *(const float4*)(Vg + (size_t)(k0 + r) * D + c);
            *(float4*)(Vs + r * SMP + c) = vv;
        }
        __syncthreads();

        float s[4][4];
#pragma unroll
        for (int i = 0; i < 4; i++)
#pragma unroll
            for (int j = 0; j < 4; j++) s[i][j] = 0.0f;

#pragma unroll 16
        for (int kk = 0; kk < 64; kk++) {
            float4 aa = *(const float4*)(Qs + kk * SMP + ty * 4);
            float4 bb = *(const float4*)(Ks + kk * SMP + tx * 4);
            float a[4] = {aa.x, aa.y, aa.z, aa.w};
            float bv[4] = {bb.x, bb.y, bb.z, bb.w};
#pragma unroll
            for (int i = 0; i < 4; i++)
#pragma unroll
                for (int j = 0; j < 4; j++) s[i][j] += a[i] * bv[j];
        }

#pragma unroll
        for (int i = 0; i < 4; i++) {
            int4 mm = *(const int4*)(Mg + (size_t)(q0 + ty * 4 + i) * S + k0 + tx * 4);
            s[i][0] = (mm.x != 0) ? s[i][0] * 0.125f : -1.0e9f;
            s[i][1] = (mm.y != 0) ? s[i][1] * 0.125f : -1.0e9f;
            s[i][2] = (mm.z != 0) ? s[i][2] * 0.125f : -1.0e9f;
            s[i][3] = (mm.w != 0) ? s[i][3] * 0.125f : -1.0e9f;
        }

#pragma unroll
        for (int i = 0; i < 4; i++) {
            float tm = fmaxf(fmaxf(s[i][0], s[i][1]), fmaxf(s[i][2], s[i][3]));
#pragma unroll
            for (int off = 1; off < 16; off <<= 1)
                tm = fmaxf(tm, __shfl_xor_sync(0xffffffffu, tm, off));
            float mnew = fmaxf(m_i[i], tm);
            float corr = __expf(m_i[i] - mnew);
            m_i[i] = mnew;
            float rs = 0.0f;
#pragma unroll
            for (int j = 0; j < 4; j++) {
                s[i][j] = __expf(s[i][j] - mnew);
                rs += s[i][j];
            }
#pragma unroll
            for (int off = 1; off < 16; off <<= 1)
                rs += __shfl_xor_sync(0xffffffffu, rs, off);
            l_i[i] = l_i[i] * corr + rs;
#pragma unroll
            for (int j = 0; j < 4; j++) o[i][j] *= corr;
        }

#pragma unroll
        for (int j = 0; j < 4; j++) {
            float4 pv = make_float4(s[0][j], s[1][j], s[2][j], s[3][j]);
            *(float4*)(Ps + (tx * 4 + j) * SMP + ty * 4) = pv;
        }
        __syncthreads();

#pragma unroll 16
        for (int cc = 0; cc < 64; cc++) {
            float4 aa = *(const float4*)(Ps + cc * SMP + ty * 4);
            float4 bb = *(const float4*)(Vs + cc * SMP + tx * 4);
            float a[4] = {aa.x, aa.y, aa.z, aa.w};
            float bv[4] = {bb.x, bb.y, bb.z, bb.w};
#pragma unroll
            for (int i = 0; i < 4; i++)
#pragma unroll
                for (int j = 0; j < 4; j++) o[i][j] += a[i] * bv[j];
        }
    }

    float* Xg = g_X + ((size_t)(b * S) + q0) * D + h * DK;
#pragma unroll
    for (int i = 0; i < 4; i++) {
        float inv = 1.0f / l_i[i];
        float4 ov = make_float4(o[i][0] * inv, o[i][1] * inv, o[i][2] * inv,
                                o[i][3] * inv);
        *(float4*)(Xg + (size_t)(ty * 4 + i) * D + tx * 4) = ov;
    }
}

// ---------------------------------------------------------------------------
extern "C" void kernel_launch(void* const* d_in, const int* in_sizes, int n_in,
                              void* d_out, int out_size) {
    const float* q = (const float*)d_in[0];
    const float* k = (const float*)d_in[1];
    const float* v = (const float*)d_in[2];
    const int* mask = (const int*)d_in[3];
    const float* Wq = (const float*)d_in[4];
    const float* Wk = (const float*)d_in[5];
    const float* Wv = (const float*)d_in[6];
    const float* Wo = (const float*)d_in[7];
    float* out = (float*)d_out;

    float *Q, *K, *V, *X;
    cudaGetSymbolAddress((void**)&Q, g_Q);
    cudaGetSymbolAddress((void**)&K, g_K);
    cudaGetSymbolAddress((void**)&V, g_V);
    cudaGetSymbolAddress((void**)&X, g_X);
    __nv_bfloat16 *Ah, *Al, *Bh, *Bl;
    cudaGetSymbolAddress((void**)&Ah, g_Ah);
    cudaGetSymbolAddress((void**)&Al, g_Al);
    cudaGetSymbolAddress((void**)&Bh, g_Bh);
    cudaGetSymbolAddress((void**)&Bl, g_Bl);

    cudaFuncSetAttribute(gemm_mma_kernel,
                         cudaFuncAttributeMaxDynamicSharedMemorySize, GEMM_SMEM);
    cudaFuncSetAttribute(attn_kernel, cudaFuncAttributeMaxDynamicSharedMemorySize,
                         (int)ATTN_SMEM);

    const int nA = NTOK * D;
    const dim3 ggrid(D / 128, NTOK / 128);  // (8, 32)
    const dim3 wgrid(D / 32, D / 32);       // (32, 32)
    const dim3 wblk(32, 8);

    split_a_kernel<<<nA / 256, 256>>>(q, Ah, Al);
    split_wt_kernel<<<wgrid, wblk>>>(Wq, Bh, Bl);
    gemm_mma_kernel<<<ggrid, 256, GEMM_SMEM>>>(Ah, Al, Bh, Bl, Q);

    split_a_kernel<<<nA / 256, 256>>>(k, Ah, Al);
    split_wt_kernel<<<wgrid, wblk>>>(Wk, Bh, Bl);
    gemm_mma_kernel<<<ggrid, 256, GEMM_SMEM>>>(Ah, Al, Bh, Bl, K);

    split_a_kernel<<<nA / 256, 256>>>(v, Ah, Al);
    split_wt_kernel<<<wgrid, wblk>>>(Wv, Bh, Bl);
    gemm_mma_kernel<<<ggrid, 256, GEMM_SMEM>>>(Ah, Al, Bh, Bl, V);

    attn_kernel<<<dim3(S / 64, H, B), 256, ATTN_SMEM>>>(mask);

    split_a_kernel<<<nA / 256, 256>>>(X, Ah, Al);
    split_wt_kernel<<<wgrid, wblk>>>(Wo, Bh, Bl);
    gemm_mma_kernel<<<ggrid, 256, GEMM_SMEM>>>(Ah, Al, Bh, Bl, out);
}

// round 4
// speedup vs baseline: 3.3341x; 2.4000x over previous
#include <cuda_runtime.h>
#include <cuda_bf16.h>
#include <cuda_fp16.h>
#include <stdint.h>
#include <math.h>

#define B 2
#define S 2048
#define D 1024
#define H 16
#define DK 64
#define NTOK (B * S)

// Scratch (allocation-free rule: __device__ globals)
__device__ __half g_Qh[(size_t)NTOK * D];
__device__ __half g_Kh[(size_t)NTOK * D];
__device__ __half g_Vh[(size_t)NTOK * D];
__device__ __nv_bfloat16 g_Ah[(size_t)NTOK * D];
__device__ __nv_bfloat16 g_Al[(size_t)NTOK * D];
__device__ __nv_bfloat16 g_Bh[(size_t)D * D];
__device__ __nv_bfloat16 g_Bl[(size_t)D * D];

// ---------------------------------------------------------------------------
// helpers (sm_80-level PTX: ldmatrix / mma.sync / cp.async)
// ---------------------------------------------------------------------------
__device__ __forceinline__ uint32_t smem_u32(const void* p) {
    uint32_t a;
    asm("{ .reg .u64 t; cvta.to.shared.u64 t, %1; cvt.u32.u64 %0, t; }"
        : "=r"(a) : "l"(p));
    return a;
}

#define LDX4(r, addr)                                                          \
    asm volatile(                                                              \
        "ldmatrix.sync.aligned.m8n8.x4.shared.b16 {%0,%1,%2,%3}, [%4];"        \
        : "=r"((r)[0]), "=r"((r)[1]), "=r"((r)[2]), "=r"((r)[3])               \
        : "r"(addr))

#define LDX4T(r, addr)                                                         \
    asm volatile(                                                              \
        "ldmatrix.sync.aligned.m8n8.x4.trans.shared.b16 {%0,%1,%2,%3}, [%4];"  \
        : "=r"((r)[0]), "=r"((r)[1]), "=r"((r)[2]), "=r"((r)[3])               \
        : "r"(addr))

#define MMA16816(d, a, b)                                                      \
    asm volatile(                                                              \
        "mma.sync.aligned.m16n8k16.row.col.f32.bf16.bf16.f32 "                 \
        "{%0,%1,%2,%3},{%4,%5,%6,%7},{%8,%9},{%0,%1,%2,%3};"                   \
        : "+f"((d)[0]), "+f"((d)[1]), "+f"((d)[2]), "+f"((d)[3])               \
        : "r"((a)[0]), "r"((a)[1]), "r"((a)[2]), "r"((a)[3]),                  \
          "r"((b)[0]), "r"((b)[1]))

#define MMA16816H(d, a, b)                                                     \
    asm volatile(                                                              \
        "mma.sync.aligned.m16n8k16.row.col.f32.f16.f16.f32 "                   \
        "{%0,%1,%2,%3},{%4,%5,%6,%7},{%8,%9},{%0,%1,%2,%3};"                   \
        : "+f"((d)[0]), "+f"((d)[1]), "+f"((d)[2]), "+f"((d)[3])               \
        : "r"((a)[0]), "r"((a)[1]), "r"((a)[2]), "r"((a)[3]),                  \
          "r"((b)[0]), "r"((b)[1]))

#define CP_ASYNC16(dst, src)                                                   \
    asm volatile("cp.async.cg.shared.global [%0], [%1], 16;" ::"r"(dst),       \
                 "l"(src))
#define CP_COMMIT() asm volatile("cp.async.commit_group;" ::: "memory")
#define CP_WAIT0() asm volatile("cp.async.wait_group 0;" ::: "memory")
#define CP_WAIT1() asm volatile("cp.async.wait_group 1;" ::: "memory")

__device__ __forceinline__ float fex2(float x) {
    float r;
    asm("ex2.approx.f32 %0, %1;" : "=f"(r) : "f"(x));
    return r;
}

__device__ __forceinline__ uint32_t packh2(float a, float b) {
    __half2 t = __floats2half2_rn(a, b);
    return *(uint32_t*)&t;
}

// ---------------------------------------------------------------------------
// Split kernels: fp32 -> bf16 hi + bf16 lo (residual)
// ---------------------------------------------------------------------------
__global__ void __launch_bounds__(256) split_a_kernel(
    const float* __restrict__ A, __nv_bfloat16* __restrict__ Ah,
    __nv_bfloat16* __restrict__ Al) {
    int i = blockIdx.x * 256 + threadIdx.x;
    float x = A[i];
    __nv_bfloat16 h = __float2bfloat16(x);
    Ah[i] = h;
    Al[i] = __float2bfloat16(x - __bfloat162float(h));
}

// W [K,N] row-major -> Wt [N,K] row-major, split into hi/lo bf16
__global__ void __launch_bounds__(256) split_wt_kernel(
    const float* __restrict__ W, __nv_bfloat16* __restrict__ Bh,
    __nv_bfloat16* __restrict__ Bl) {
    __shared__ float t[32][33];
    const int n0 = blockIdx.x * 32, k0 = blockIdx.y * 32;
    const int tx = threadIdx.x, ty = threadIdx.y;  // 32 x 8
#pragma unroll
    for (int r = ty; r < 32; r += 8)
        t[r][tx] = W[(size_t)(k0 + r) * D + n0 + tx];
    __syncthreads();
#pragma unroll
    for (int r = ty; r < 32; r += 8) {
        float x = t[tx][r];  // = W[k0+tx][n0+r]
        __nv_bfloat16 h = __float2bfloat16(x);
        size_t o = (size_t)(n0 + r) * D + k0 + tx;
        Bh[o] = h;
        Bl[o] = __float2bfloat16(x - __bfloat162float(h));
    }
}

// ---------------------------------------------------------------------------
// mma.sync GEMM: C = (Ah+Al)[M x K] * (Bh+Bl)^T (B stored [N,K]).
// CTA 128x128, BK=64, 8 warps (2m x 4n), warp tile 64x32.
// HALF_OUT: write __half C; else fp32.
// ---------------------------------------------------------------------------
#define TILE_BYTES 16384
#define STAGE_BYTES 65536
#define GEMM_SMEM (2 * STAGE_BYTES)

template <bool HALF_OUT>
__global__ void __launch_bounds__(256, 1) gemm_mma_kernel(
    const __nv_bfloat16* __restrict__ Ah, const __nv_bfloat16* __restrict__ Al,
    const __nv_bfloat16* __restrict__ Bh, const __nv_bfloat16* __restrict__ Bl,
    void* __restrict__ Cv) {
    extern __shared__ char sm[];
    const uint32_t sb = smem_u32(sm);
    const int tid = threadIdx.x;
    const int lid = tid & 31;
    const int wid = tid >> 5;
    const int wm = wid & 1;
    const int wn = wid >> 1;
    const int rowB = blockIdx.y * 128;
    const int colB = blockIdx.x * 128;

    float d[4][4][4];
#pragma unroll
    for (int mi = 0; mi < 4; mi++)
#pragma unroll
        for (int nj = 0; nj < 4; nj++)
#pragma unroll
            for (int e = 0; e < 4; e++) d[mi][nj][e] = 0.0f;

    auto load_stage = [&](int stg, int kt) {
        const uint32_t base = sb + stg * STAGE_BYTES;
#pragma unroll
        for (int i = 0; i < 16; i++) {
            const int idx = tid + i * 256;
            const int tile = idx >> 10;
            const int r = (idx >> 3) & 127;
            const int c = idx & 7;
            const __nv_bfloat16* g;
            if (tile == 0)      g = Ah + (size_t)(rowB + r) * D;
            else if (tile == 1) g = Al + (size_t)(rowB + r) * D;
            else if (tile == 2) g = Bh + (size_t)(colB + r) * D;
            else                g = Bl + (size_t)(colB + r) * D;
            g += kt * 64 + c * 8;
            const uint32_t dst =
                base + tile * TILE_BYTES + r * 128 + ((c ^ (r & 7)) << 4);
            CP_ASYNC16(dst, g);
        }
        CP_COMMIT();
    };

    load_stage(0, 0);

    for (int kt = 0; kt < 16; kt++) {
        const int cur = kt & 1;
        CP_WAIT0();
        __syncthreads();
        if (kt + 1 < 16) load_stage(cur ^ 1, kt + 1);

        const uint32_t sA = sb + cur * STAGE_BYTES;
        const uint32_t sB = sA + 2 * TILE_BYTES;

#pragma unroll
        for (int kk = 0; kk < 4; kk++) {
            uint32_t ah[4][4], al[4][4], bh[4][2], bl[4][2];
#pragma unroll
            for (int mi = 0; mi < 4; mi++) {
                const int row = wm * 64 + mi * 16 + (lid & 15);
                const int c = kk * 2 + (lid >> 4);
                const uint32_t off = row * 128 + ((c ^ (row & 7)) << 4);
                LDX4(ah[mi], sA + off);
                LDX4(al[mi], sA + TILE_BYTES + off);
            }
#pragma unroll
            for (int jj = 0; jj < 2; jj++) {
                const int m = lid >> 3;
                const int n = wn * 32 + jj * 16 + ((m >> 1) << 3) + (lid & 7);
                const int c = kk * 2 + (m & 1);
                const uint32_t off = n * 128 + ((c ^ (n & 7)) << 4);
                uint32_t t[4];
                LDX4(t, sB + off);
                bh[jj * 2][0] = t[0];
                bh[jj * 2][1] = t[1];
                bh[jj * 2 + 1][0] = t[2];
                bh[jj * 2 + 1][1] = t[3];
                LDX4(t, sB + TILE_BYTES + off);
                bl[jj * 2][0] = t[0];
                bl[jj * 2][1] = t[1];
                bl[jj * 2 + 1][0] = t[2];
                bl[jj * 2 + 1][1] = t[3];
            }
#pragma unroll
            for (int mi = 0; mi < 4; mi++)
#pragma unroll
                for (int nj = 0; nj < 4; nj++) {
                    MMA16816(d[mi][nj], ah[mi], bh[nj]);
                    MMA16816(d[mi][nj], ah[mi], bl[nj]);
                    MMA16816(d[mi][nj], al[mi], bh[nj]);
                }
        }
    }

#pragma unroll
    for (int mi = 0; mi < 4; mi++) {
        const int r0 = rowB + wm * 64 + mi * 16 + (lid >> 2);
#pragma unroll
        for (int nj = 0; nj < 4; nj++) {
            const int col = colB + wn * 32 + nj * 8 + (lid & 3) * 2;
            if (HALF_OUT) {
                __half* C = (__half*)Cv;
                *(__half2*)(C + (size_t)r0 * D + col) =
                    __floats2half2_rn(d[mi][nj][0], d[mi][nj][1]);
                *(__half2*)(C + (size_t)(r0 + 8) * D + col) =
                    __floats2half2_rn(d[mi][nj][2], d[mi][nj][3]);
            } else {
                float* C = (float*)Cv;
                *(float2*)(C + (size_t)r0 * D + col) =
                    make_float2(d[mi][nj][0], d[mi][nj][1]);
                *(float2*)(C + (size_t)(r0 + 8) * D + col) =
                    make_float2(d[mi][nj][2], d[mi][nj][3]);
            }
        }
    }
}

// ---------------------------------------------------------------------------
// fp16 tensor-core flash attention.
// CTA = (q-tile of 128, head, batch). 8 warps x 16 q-rows. Bc = 64.
// SMEM: Q 128x64 half (16KB) + 2 stages of (K 64x64 + V 64x64) half (16KB ea).
// Output: X normalized, written as bf16 hi/lo into g_Ah/g_Al.
// ---------------------------------------------------------------------------
#define AQ_OFF 0
#define AST_OFF 16384
#define AST_SZ 16384
#define AV_OFF 8192
#define ATTN_SMEM (16384 + 2 * 16384)
#define SCL2E 0.18033688011112042f  // 0.125 * log2(e)

__global__ void __launch_bounds__(256, 1) attn_kernel(const int* __restrict__ mask) {
    extern __shared__ char sm[];
    const uint32_t sb = smem_u32(sm);
    const int tid = threadIdx.x;
    const int lid = tid & 31;
    const int wid = tid >> 5;
    const int w0 = wid * 16;
    const int q0 = blockIdx.x * 128;
    const int h = blockIdx.y;
    const int b = blockIdx.z;

    const __half* Qg = g_Qh + ((size_t)(b * S + q0)) * D + h * DK;
    const __half* Kg = g_Kh + ((size_t)(b * S)) * D + h * DK;
    const __half* Vg = g_Vh + ((size_t)(b * S)) * D + h * DK;
    const int* Mg = mask + (size_t)b * S * S;

    auto load_kv = [&](int stg, int kt) {
        const uint32_t base = sb + AST_OFF + stg * AST_SZ;
        const int k0 = kt * 64;
#pragma unroll
        for (int i = 0; i < 4; i++) {
            const int idx = tid + i * 256;
            const int tile = idx >> 9;        // 0 = K, 1 = V
            const int r = (idx >> 3) & 63;
            const int c = idx & 7;
            const __half* g = (tile == 0 ? Kg : Vg) + (size_t)(k0 + r) * D + c * 8;
            const uint32_t dst =
                base + tile * 8192 + r * 128 + ((c ^ (r & 7)) << 4);
            CP_ASYNC16(dst, g);
        }
    };

    // Q tile load (group 0 together with stage 0)
#pragma unroll
    for (int i = 0; i < 4; i++) {
        const int idx = tid + i * 256;
        const int r = idx >> 3;
        const int c = idx & 7;
        const __half* g = Qg + (size_t)r * D + c * 8;
        const uint32_t dst = sb + AQ_OFF + r * 128 + ((c ^ (r & 7)) << 4);
        CP_ASYNC16(dst, g);
    }
    load_kv(0, 0);
    CP_COMMIT();

    uint32_t qf[4][4];
    float m0 = -1e30f, m1 = -1e30f, l0 = 0.0f, l1 = 0.0f;
    float o[8][4];
#pragma unroll
    for (int oj = 0; oj < 8; oj++)
#pragma unroll
        for (int e = 0; e < 4; e++) o[oj][e] = 0.0f;

    const int rr0 = lid >> 2;          // local row within 16-row warp tile
    const int cc0 = (lid & 3) * 2;     // local col pair within 8-col tile

    for (int kt = 0; kt < 32; kt++) {
        const int cur = kt & 1;
        const int k0 = kt * 64;
        if (kt + 1 < 32) {
            load_kv(cur ^ 1, kt + 1);
            CP_COMMIT();
            CP_WAIT1();
        } else {
            CP_WAIT0();
        }
        __syncthreads();

        if (kt == 0) {
            // load Q fragments once (group 0 has landed)
#pragma unroll
            for (int ks = 0; ks < 4; ks++) {
                const int row = w0 + ((lid >> 3) & 1) * 8 + (lid & 7);
                const int c = ks * 2 + (lid >> 4);
                LDX4(qf[ks], sb + AQ_OFF + row * 128 + ((c ^ (row & 7)) << 4));
            }
        }

        const uint32_t sK = sb + AST_OFF + cur * AST_SZ;
        const uint32_t sV = sK + AV_OFF;

        // ---- S = Q K^T  (128 x 64 per CTA; this warp: 16 x 64)
        float s[8][4];
#pragma unroll
        for (int nj = 0; nj < 8; nj++) {
#pragma unroll
            for (int e = 0; e < 4; e++) s[nj][e] = 0.0f;
        }
#pragma unroll
        for (int nj = 0; nj < 8; nj++) {
            uint32_t bf[4][2];
#pragma unroll
            for (int kp = 0; kp < 2; kp++) {
                const int row = nj * 8 + (lid & 7);
                const int c = kp * 4 + (lid >> 3);
                uint32_t t[4];
                LDX4(t, sK + row * 128 + ((c ^ (row & 7)) << 4));
                bf[kp * 2][0] = t[0];
                bf[kp * 2][1] = t[1];
                bf[kp * 2 + 1][0] = t[2];
                bf[kp * 2 + 1][1] = t[3];
            }
#pragma unroll
            for (int ks = 0; ks < 4; ks++) MMA16816H(s[nj], qf[ks], bf[ks]);
        }

        // ---- scale (log2 domain) + mask
        const int gr0 = q0 + w0 + rr0;
#pragma unroll
        for (int nj = 0; nj < 8; nj++) {
            const int col = k0 + nj * 8 + cc0;
            int2 ma = *(const int2*)(Mg + (size_t)gr0 * S + col);
            int2 mb = *(const int2*)(Mg + (size_t)(gr0 + 8) * S + col);
            s[nj][0] = ma.x ? s[nj][0] * SCL2E : -1e9f;
            s[nj][1] = ma.y ? s[nj][1] * SCL2E : -1e9f;
            s[nj][2] = mb.x ? s[nj][2] * SCL2E : -1e9f;
            s[nj][3] = mb.y ? s[nj][3] * SCL2E : -1e9f;
        }

        // ---- online softmax (rows rr0, rr0+8; 4-lane groups share a row)
        float mx0 = -1e30f, mx1 = -1e30f;
#pragma unroll
        for (int nj = 0; nj < 8; nj++) {
            mx0 = fmaxf(mx0, fmaxf(s[nj][0], s[nj][1]));
            mx1 = fmaxf(mx1, fmaxf(s[nj][2], s[nj][3]));
        }
        mx0 = fmaxf(mx0, __shfl_xor_sync(0xffffffffu, mx0, 1));
        mx0 = fmaxf(mx0, __shfl_xor_sync(0xffffffffu, mx0, 2));
        mx1 = fmaxf(mx1, __shfl_xor_sync(0xffffffffu, mx1, 1));
        mx1 = fmaxf(mx1, __shfl_xor_sync(0xffffffffu, mx1, 2));
        const float mn0 = fmaxf(m0, mx0);
        const float mn1 = fmaxf(m1, mx1);
        const float c0 = fex2(m0 - mn0);
        const float c1 = fex2(m1 - mn1);
        m0 = mn0;
        m1 = mn1;
        float sum0 = 0.0f, sum1 = 0.0f;
#pragma unroll
        for (int nj = 0; nj < 8; nj++) {
            s[nj][0] = fex2(s[nj][0] - mn0);
            s[nj][1] = fex2(s[nj][1] - mn0);
            s[nj][2] = fex2(s[nj][2] - mn1);
            s[nj][3] = fex2(s[nj][3] - mn1);
            sum0 += s[nj][0] + s[nj][1];
            sum1 += s[nj][2] + s[nj][3];
        }
        sum0 += __shfl_xor_sync(0xffffffffu, sum0, 1);
        sum0 += __shfl_xor_sync(0xffffffffu, sum0, 2);
        sum1 += __shfl_xor_sync(0xffffffffu, sum1, 1);
        sum1 += __shfl_xor_sync(0xffffffffu, sum1, 2);
        l0 = l0 * c0 + sum0;
        l1 = l1 * c1 + sum1;
#pragma unroll
        for (int oj = 0; oj < 8; oj++) {
            o[oj][0] *= c0;
            o[oj][1] *= c0;
            o[oj][2] *= c1;
            o[oj][3] *= c1;
        }

        // ---- pack P fragments (registers only)
        uint32_t pf[4][4];
#pragma unroll
        for (int ktile = 0; ktile < 4; ktile++) {
            pf[ktile][0] = packh2(s[2 * ktile][0], s[2 * ktile][1]);
            pf[ktile][1] = packh2(s[2 * ktile][2], s[2 * ktile][3]);
            pf[ktile][2] = packh2(s[2 * ktile + 1][0], s[2 * ktile + 1][1]);
            pf[ktile][3] = packh2(s[2 * ktile + 1][2], s[2 * ktile + 1][3]);
        }

        // ---- O += P V   (V^T fragments via ldmatrix.trans)
#pragma unroll
        for (int p = 0; p < 4; p++) {  // pairs of dk n-tiles (2p, 2p+1)
#pragma unroll
            for (int ktile = 0; ktile < 4; ktile++) {
                const int row = ktile * 16 + ((lid >> 3) & 1) * 8 + (lid & 7);
                const int c = 2 * p + (lid >> 4);
                uint32_t t[4];
                LDX4T(t, sV + row * 128 + ((c ^ (row & 7)) << 4));
                uint32_t bA[2] = {t[0], t[1]};
                uint32_t bB[2] = {t[2], t[3]};
                MMA16816H(o[2 * p], pf[ktile], bA);
                MMA16816H(o[2 * p + 1], pf[ktile], bB);
            }
        }
        __syncthreads();
    }

    // ---- epilogue: normalize + write X as bf16 hi/lo (fused split for Wo GEMM)
    const float inv0 = 1.0f / l0;
    const float inv1 = 1.0f / l1;
    const size_t tok0 = (size_t)(b * S + q0 + w0 + rr0);
    const size_t tok1 = tok0 + 8;
#pragma unroll
    for (int oj = 0; oj < 8; oj++) {
        const int col = h * DK + oj * 8 + cc0;
        float x0 = o[oj][0] * inv0, x1 = o[oj][1] * inv0;
        float x2 = o[oj][2] * inv1, x3 = o[oj][3] * inv1;
        __nv_bfloat16 h0 = __float2bfloat16(x0), h1 = __float2bfloat16(x1);
        __nv_bfloat16 h2 = __float2bfloat16(x2), h3 = __float2bfloat16(x3);
        __nv_bfloat162 hi01; hi01.x = h0; hi01.y = h1;
        __nv_bfloat162 hi23; hi23.x = h2; hi23.y = h3;
        *(__nv_bfloat162*)(g_Ah + tok0 * D + col) = hi01;
        *(__nv_bfloat162*)(g_Ah + tok1 * D + col) = hi23;
        __nv_bfloat162 lo01, lo23;
        lo01.x = __float2bfloat16(x0 - __bfloat162float(h0));
        lo01.y = __float2bfloat16(x1 - __bfloat162float(h1));
        lo23.x = __float2bfloat16(x2 - __bfloat162float(h2));
        lo23.y = __float2bfloat16(x3 - __bfloat162float(h3));
        *(__nv_bfloat162*)(g_Al + tok0 * D + col) = lo01;
        *(__nv_bfloat162*)(g_Al + tok1 * D + col) = lo23;
    }
}

// ---------------------------------------------------------------------------
extern "C" void kernel_launch(void* const* d_in, const int* in_sizes, int n_in,
                              void* d_out, int out_size) {
    const float* q = (const float*)d_in[0];
    const float* k = (const float*)d_in[1];
    const float* v = (const float*)d_in[2];
    const int* mask = (const int*)d_in[3];
    const float* Wq = (const float*)d_in[4];
    const float* Wk = (const float*)d_in[5];
    const float* Wv = (const float*)d_in[6];
    const float* Wo = (const float*)d_in[7];
    float* out = (float*)d_out;

    __half *Qh, *Kh, *Vh;
    cudaGetSymbolAddress((void**)&Qh, g_Qh);
    cudaGetSymbolAddress((void**)&Kh, g_Kh);
    cudaGetSymbolAddress((void**)&Vh, g_Vh);
    __nv_bfloat16 *Ah, *Al, *Bh, *Bl;
    cudaGetSymbolAddress((void**)&Ah, g_Ah);
    cudaGetSymbolAddress((void**)&Al, g_Al);
    cudaGetSymbolAddress((void**)&Bh, g_Bh);
    cudaGetSymbolAddress((void**)&Bl, g_Bl);

    cudaFuncSetAttribute(gemm_mma_kernel<true>,
                         cudaFuncAttributeMaxDynamicSharedMemorySize, GEMM_SMEM);
    cudaFuncSetAttribute(gemm_mma_kernel<false>,
                         cudaFuncAttributeMaxDynamicSharedMemorySize, GEMM_SMEM);
    cudaFuncSetAttribute(attn_kernel,
                         cudaFuncAttributeMaxDynamicSharedMemorySize, ATTN_SMEM);

    const int nA = NTOK * D;
    const dim3 ggrid(D / 128, NTOK / 128);  // (8, 32)
    const dim3 wgrid(D / 32, D / 32);       // (32, 32)
    const dim3 wblk(32, 8);

    split_a_kernel<<<nA / 256, 256>>>(q, Ah, Al);
    split_wt_kernel<<<wgrid, wblk>>>(Wq, Bh, Bl);
    gemm_mma_kernel<true><<<ggrid, 256, GEMM_SMEM>>>(Ah, Al, Bh, Bl, Qh);

    split_a_kernel<<<nA / 256, 256>>>(k, Ah, Al);
    split_wt_kernel<<<wgrid, wblk>>>(Wk, Bh, Bl);
    gemm_mma_kernel<true><<<ggrid, 256, GEMM_SMEM>>>(Ah, Al, Bh, Bl, Kh);

    split_a_kernel<<<nA / 256, 256>>>(v, Ah, Al);
    split_wt_kernel<<<wgrid, wblk>>>(Wv, Bh, Bl);
    gemm_mma_kernel<true><<<ggrid, 256, GEMM_SMEM>>>(Ah, Al, Bh, Bl, Vh);

    // attention writes X directly as bf16 hi/lo into g_Ah/g_Al
    attn_kernel<<<dim3(S / 128, H, B), 256, ATTN_SMEM>>>(mask);

    split_wt_kernel<<<wgrid, wblk>>>(Wo, Bh, Bl);
    gemm_mma_kernel<false><<<ggrid, 256, GEMM_SMEM>>>(Ah, Al, Bh, Bl, out);
}